// round 11
// baseline (speedup 1.0000x reference)
#include <cuda_runtime.h>
#include <cuda_bf16.h>
#include <cuda_fp16.h>
#include <cstdint>

#define D 784
#define H 1024
#define BATCH 1024
#define THREADS 512
#define R 7                      // batch rows per CTA
#define NCTAS 147                // 147*7 = 1029 >= 1024
#define CHUNK 98                 // 784 = 8 * 98 (even trip count)
#define NCHUNKS (D / CHUNK)
#define SX_BYTES (D * 8 * 4)                 // sx8[D][8]
#define SP_BYTES (CHUNK * 16 * 8 * 4)        // sp[CHUNK][16][8]
#define SMEM_BYTES (SX_BYTES + SP_BYTES)     // 75264

// Scratch (no allocations allowed).
// g_VW[i*512 + t] = ( bits(f16x2(V[i,2t], V[i,2t+1])), W[2t,i], W[2t+1,i], 0 )
__device__ float4 g_VW[D * (H / 2)];
__device__ float  g_bias[D];          // bias[i] = b[i] + 0.5 * sum_h V[i,h]

// Two tanh evaluations in ONE MUFU op via f16x2; returns packed f16x2.
__device__ __forceinline__ uint32_t tanh2pk(float a, float b) {
    uint32_t pk, tk;
    asm("cvt.rn.f16x2.f32 %0, %1, %2;" : "=r"(pk) : "f"(b), "f"(a)); // lo=a, hi=b
    asm("tanh.approx.f16x2 %0, %1;" : "=r"(tk) : "r"(pk));
    return tk;
}

__device__ __forceinline__ uint32_t hmul2(uint32_t a, uint32_t b) {
    uint32_t d;
    asm("mul.rn.f16x2 %0, %1, %2;" : "=r"(d) : "r"(a), "r"(b));
    return d;
}

__device__ __forceinline__ uint32_t hadd2(uint32_t a, uint32_t b) {
    uint32_t d;
    asm("add.rn.f16x2 %0, %1, %2;" : "=r"(d) : "r"(a), "r"(b));
    return d;
}

// Unpack packed f16x2 and sum the halves in f32.
__device__ __forceinline__ float hsum2(uint32_t pk) {
    float lo, hi;
    asm("{\n\t.reg .b16 l, h;\n\t"
        "mov.b32 {l, h}, %2;\n\t"
        "cvt.f32.f16 %0, l;\n\t"
        "cvt.f32.f16 %1, h;\n\t}"
        : "=f"(lo), "=f"(hi) : "r"(pk));
    return lo + hi;
}

// ---------------------------------------------------------------------------
// Fused prep: blockIdx.y < 32 -> build interleaved g_VW tile (transpose W via
//                                smem tile, merge with f16x2-packed V)
//             blockIdx.y == 32 -> bias[i] = b[i] + 0.5 * sum_h V[i,h]
// ---------------------------------------------------------------------------
__global__ void prep_kernel(const float* __restrict__ W,
                            const float* __restrict__ V,
                            const float* __restrict__ bvec) {
    if (blockIdx.y < 32) {
        __shared__ float tile[32][33];
        const int i0 = blockIdx.x * 32;
        const int h0 = blockIdx.y * 32;
        const int tx = threadIdx.x, ty = threadIdx.y;
        #pragma unroll
        for (int j = 0; j < 32; j += 8) {
            int ii = i0 + tx;
            if (ii < D) tile[ty + j][tx] = W[(h0 + ty + j) * D + ii];
        }
        __syncthreads();
        #pragma unroll
        for (int j = 0; j < 32; j += 8) {
            int i = i0 + ty + j;
            if (i < D && tx < 16) {
                int tcol = h0 / 2 + tx;
                float2 v2 = reinterpret_cast<const float2*>(V)[i * (H / 2) + tcol];
                __half2 hv = __floats2half2_rn(v2.x, v2.y);
                uint32_t vbits = *reinterpret_cast<uint32_t*>(&hv);
                g_VW[i * (H / 2) + tcol] =
                    make_float4(__uint_as_float(vbits),
                                tile[2 * tx][i - i0], tile[2 * tx + 1][i - i0], 0.0f);
            }
        }
    } else {
        int lane = threadIdx.x;
        int w    = threadIdx.y;
        #pragma unroll
        for (int k = 0; k < 4; k++) {
            int i = blockIdx.x * 32 + w * 4 + k;
            if (i >= D) continue;
            float s = 0.0f;
            #pragma unroll
            for (int j = 0; j < H / 32; j++) s += V[i * H + j * 32 + lane];
            #pragma unroll
            for (int o = 16; o > 0; o >>= 1)
                s += __shfl_xor_sync(0xffffffffu, s, o);
            if (lane == 0) g_bias[i] = bvec[i] + 0.5f * s;
        }
    }
}

// ---------------------------------------------------------------------------
// Main: one CTA per 7 batch rows; 512 threads (16 warps), 2 h per lane.
// Software-pipelined (next step's vw LDG.128 + xs LDS.128 prefetched).
// Dot product: tanh2 packed output * f16x2-packed V via ONE HMUL2 per row.
// Butterfly reduction runs on packed u32 with HADD2 (round-6 shape);
// halves summed in f32 only at the end. Accumulators stay f32.
// ---------------------------------------------------------------------------
__global__ void __launch_bounds__(THREADS, 1)
nade_main(const float* __restrict__ pixels,
          const float* __restrict__ c,
          float* __restrict__ out) {
    extern __shared__ char smem_raw[];
    float* sx8 = reinterpret_cast<float*>(smem_raw);              // [D][8]
    float* sp  = reinterpret_cast<float*>(smem_raw + SX_BYTES);   // [CHUNK][16][8]

    const int b0   = blockIdx.x * R;
    const int t    = threadIdx.x;
    const int lane = t & 31;
    const int wid  = t >> 5;

    for (int i = t; i < D; i += THREADS) {
        #pragma unroll
        for (int r = 0; r < R; r++) {
            int br = min(b0 + r, BATCH - 1);
            sx8[i * 8 + r] = 0.5f * pixels[br * D + i];
        }
        sx8[i * 8 + 7] = 0.0f;
    }

    float2 A[R];
    {
        float2 cc = reinterpret_cast<const float2*>(c)[t];
        cc.x *= 0.5f; cc.y *= 0.5f;
        #pragma unroll
        for (int r = 0; r < R; r++) A[r] = cc;
    }
    __syncthreads();

    const bool lo16 = (lane & 16) == 0;
    const bool lo8  = (lane & 8)  == 0;
    const bool lo4  = (lane & 4)  == 0;
    const int rowmap = ((lane >> 4) & 1) | (((lane >> 3) & 1) << 1)
                     | (((lane >> 2) & 1) << 2);
    const bool is_head = (lane & 3) == 0;

    const float4* __restrict__ VW4 = g_VW;

    // Prime the pipeline with step 0's operands.
    float4 vw  = VW4[t];
    float4 x03, x47;
    {
        const float4* xs4 = reinterpret_cast<const float4*>(&sx8[0]);
        x03 = xs4[0];
        x47 = xs4[1];
    }

    for (int ch = 0; ch < NCHUNKS; ch++) {
        const int ibase = ch * CHUNK;

        #pragma unroll 2
        for (int il = 0; il < CHUNK; il++) {
            const int i = ibase + il;
            // ---- prefetch next step's operands (fully overlapped) ----
            const int ip = (i + 1 < D) ? (i + 1) : (D - 1);
            float4 vw_n = VW4[ip * (H / 2) + t];
            const float4* xs4n = reinterpret_cast<const float4*>(&sx8[ip * 8]);
            float4 x03_n = xs4n[0];
            float4 x47_n = xs4n[1];

            // ---- compute current step ----
            const uint32_t vpk = __float_as_uint(vw.x);
            uint32_t p0 = hmul2(tanh2pk(A[0].x, A[0].y), vpk);
            uint32_t p1 = hmul2(tanh2pk(A[1].x, A[1].y), vpk);
            uint32_t p2 = hmul2(tanh2pk(A[2].x, A[2].y), vpk);
            uint32_t p3 = hmul2(tanh2pk(A[3].x, A[3].y), vpk);
            uint32_t p4 = hmul2(tanh2pk(A[4].x, A[4].y), vpk);
            uint32_t p5 = hmul2(tanh2pk(A[5].x, A[5].y), vpk);
            uint32_t p6 = hmul2(tanh2pk(A[6].x, A[6].y), vpk);

            A[0].x = fmaf(vw.y, x03.x, A[0].x);
            A[0].y = fmaf(vw.z, x03.x, A[0].y);
            A[1].x = fmaf(vw.y, x03.y, A[1].x);
            A[1].y = fmaf(vw.z, x03.y, A[1].y);
            A[2].x = fmaf(vw.y, x03.z, A[2].x);
            A[2].y = fmaf(vw.z, x03.z, A[2].y);
            A[3].x = fmaf(vw.y, x03.w, A[3].x);
            A[3].y = fmaf(vw.z, x03.w, A[3].y);
            A[4].x = fmaf(vw.y, x47.x, A[4].x);
            A[4].y = fmaf(vw.z, x47.x, A[4].y);
            A[5].x = fmaf(vw.y, x47.y, A[5].x);
            A[5].y = fmaf(vw.z, x47.y, A[5].y);
            A[6].x = fmaf(vw.y, x47.z, A[6].x);
            A[6].y = fmaf(vw.z, x47.z, A[6].y);

            // Packed butterfly (round-6 shape: shuffles issued before select).
            uint32_t e, f;
            e = __shfl_xor_sync(0xffffffffu, p0, 16);
            f = __shfl_xor_sync(0xffffffffu, p1, 16);
            uint32_t q01 = lo16 ? hadd2(p0, e) : hadd2(p1, f);
            e = __shfl_xor_sync(0xffffffffu, p2, 16);
            f = __shfl_xor_sync(0xffffffffu, p3, 16);
            uint32_t q23 = lo16 ? hadd2(p2, e) : hadd2(p3, f);
            e = __shfl_xor_sync(0xffffffffu, p4, 16);
            f = __shfl_xor_sync(0xffffffffu, p5, 16);
            uint32_t q45 = lo16 ? hadd2(p4, e) : hadd2(p5, f);
            e = __shfl_xor_sync(0xffffffffu, p6, 16);
            uint32_t q67 = lo16 ? hadd2(p6, e) : 0u;   // slot 7 is zero

            e = __shfl_xor_sync(0xffffffffu, q01, 8);
            f = __shfl_xor_sync(0xffffffffu, q23, 8);
            uint32_t q0123 = lo8 ? hadd2(q01, e) : hadd2(q23, f);
            e = __shfl_xor_sync(0xffffffffu, q45, 8);
            f = __shfl_xor_sync(0xffffffffu, q67, 8);
            uint32_t q4567 = lo8 ? hadd2(q45, e) : hadd2(q67, f);

            e = __shfl_xor_sync(0xffffffffu, q0123, 4);
            f = __shfl_xor_sync(0xffffffffu, q4567, 4);
            uint32_t qq = lo4 ? hadd2(q0123, e) : hadd2(q4567, f);

            qq = hadd2(qq, __shfl_xor_sync(0xffffffffu, qq, 2));
            qq = hadd2(qq, __shfl_xor_sync(0xffffffffu, qq, 1));

            // Halves -> f32 once, at the end.
            float s = hsum2(qq);
            if (is_head) sp[(il * 16 + wid) * 8 + rowmap] = s;

            // ---- rotate pipeline ----
            vw = vw_n; x03 = x03_n; x47 = x47_n;
        }

        __syncthreads();

        // Epilogue: for each (step, row) sum the 16 warp partials.
        for (int o = t; o < CHUNK * R; o += THREADS) {
            int il = o / R, r = o % R;
            float s = 0.0f;
            #pragma unroll
            for (int wi = 0; wi < 16; wi++)
                s += sp[(il * 16 + wi) * 8 + r];
            int i = ibase + il;
            int b = b0 + r;
            if (b < BATCH) out[b * D + i] = fmaf(0.5f, s, g_bias[i]);
        }

        __syncthreads();
    }
}

// ---------------------------------------------------------------------------
extern "C" void kernel_launch(void* const* d_in, const int* in_sizes, int n_in,
                              void* d_out, int out_size) {
    const float* pixels = (const float*)d_in[0];   // [1024, 784]
    const float* W      = (const float*)d_in[1];   // [1024, 784]
    const float* c      = (const float*)d_in[2];   // [1024]
    const float* V      = (const float*)d_in[3];   // [784, 1024]
    const float* bvec   = (const float*)d_in[4];   // [784]
    float* out          = (float*)d_out;           // [1024, 784]

    cudaFuncSetAttribute(nade_main, cudaFuncAttributeMaxDynamicSharedMemorySize,
                         SMEM_BYTES);
    cudaFuncSetAttribute(nade_main, cudaFuncAttributePreferredSharedMemoryCarveout,
                         100);

    prep_kernel<<<dim3(25, 33), dim3(32, 8)>>>(W, V, bvec);
    nade_main<<<NCTAS, THREADS, SMEM_BYTES>>>(pixels, c, out);
}